// round 14
// baseline (speedup 1.0000x reference)
#include <cuda_runtime.h>
#include <cuda_fp16.h>
#include <cstddef>
#include <cstdint>

// Problem constants
constexpr int Bb  = 64;
constexpr int Nn  = 197;
constexpr int Cc  = 768;
constexpr int Hh  = 12;
constexpr int Dd  = 64;
constexpr int M_TOT = Bb * Nn;        // 12608
constexpr int SLD  = 212;             // S row stride (floats): 208 cols + 4 pad

// Scratch (device globals) — fp16
__device__ __half g_q[(size_t)Bb * Hh * Nn * Dd];
__device__ __half g_k[(size_t)Bb * Hh * Nn * Dd];
__device__ __half g_v[(size_t)Bb * Hh * Nn * Dd];
__device__ float  g_rpb[(size_t)Hh * Nn * Nn];
__device__ __half g_o[(size_t)Bb * Nn * Cc];
// pre-converted fp16 inputs
__device__ __half g_xh[(size_t)M_TOT * Cc];          // x
__device__ __half g_wh[(size_t)3 * Cc * Cc];         // qkv_w
__device__ __half g_pwh[(size_t)Cc * Cc];            // proj_w

// ---------------------------------------------------------------------------
// helpers
// ---------------------------------------------------------------------------
__device__ __forceinline__ unsigned pack2(float x, float y) {
    __half2 h = __float22half2_rn(make_float2(x, y));
    return *reinterpret_cast<unsigned*>(&h);
}

__device__ __forceinline__ void mma_f16(
    float& c0, float& c1, float& c2, float& c3,
    unsigned a0, unsigned a1, unsigned a2, unsigned a3,
    unsigned b0, unsigned b1)
{
    asm volatile(
        "mma.sync.aligned.m16n8k16.row.col.f32.f16.f16.f32 "
        "{%0,%1,%2,%3},{%4,%5,%6,%7},{%8,%9},{%0,%1,%2,%3};\n"
        : "+f"(c0), "+f"(c1), "+f"(c2), "+f"(c3)
        : "r"(a0), "r"(a1), "r"(a2), "r"(a3), "r"(b0), "r"(b1));
}

__device__ __forceinline__ void ldsm_x4(
    unsigned& r0, unsigned& r1, unsigned& r2, unsigned& r3, unsigned addr)
{
    asm volatile("ldmatrix.sync.aligned.m8n8.x4.shared.b16 {%0,%1,%2,%3}, [%4];"
                 : "=r"(r0), "=r"(r1), "=r"(r2), "=r"(r3) : "r"(addr));
}

__device__ __forceinline__ void ldsm_x4_trans(
    unsigned& r0, unsigned& r1, unsigned& r2, unsigned& r3, unsigned addr)
{
    asm volatile("ldmatrix.sync.aligned.m8n8.x4.trans.shared.b16 {%0,%1,%2,%3}, [%4];"
                 : "=r"(r0), "=r"(r1), "=r"(r2), "=r"(r3) : "r"(addr));
}

__device__ __forceinline__ void cp16(unsigned dst, const void* src) {
    asm volatile("cp.async.ca.shared.global [%0], [%1], 16;"
                 :: "r"(dst), "l"(src) : "memory");
}
// predicated: bytes==0 -> zero-fill destination
__device__ __forceinline__ void cp16p(unsigned dst, const void* src, unsigned bytes) {
    asm volatile("cp.async.ca.shared.global [%0], [%1], 16, %2;"
                 :: "r"(dst), "l"(src), "r"(bytes) : "memory");
}
__device__ __forceinline__ void cp_commit() {
    asm volatile("cp.async.commit_group;" ::: "memory");
}
template <int N>
__device__ __forceinline__ void cp_wait() {
    asm volatile("cp.async.wait_group %0;" :: "n"(N) : "memory");
}

// ---------------------------------------------------------------------------
// Kernel 0: fp32 -> fp16 conversion (x, qkv_w, proj_w)
// ---------------------------------------------------------------------------
__global__ void cvt_kernel(const float* __restrict__ src, __half* __restrict__ dst,
                           int n4) {
    int i = blockIdx.x * blockDim.x + threadIdx.x;
    if (i >= n4) return;
    float4 f = ((const float4*)src)[i];
    ((uint2*)dst)[i] = make_uint2(pack2(f.x, f.y), pack2(f.z, f.w));
}

// ---------------------------------------------------------------------------
// Kernel 1: relative position bias gather
// ---------------------------------------------------------------------------
__global__ void rpb_kernel(const float* __restrict__ rel_table) {
    int tid = blockIdx.x * blockDim.x + threadIdx.x;
    const int total = Hh * Nn * Nn;
    if (tid >= total) return;
    int h = tid / (Nn * Nn);
    int r = tid % (Nn * Nn);
    int i = r / Nn, j = r % Nn;
    int idx;
    if (i == 0 && j == 0)      idx = 731;
    else if (i == 0)           idx = 729;
    else if (j == 0)           idx = 730;
    else {
        int a = i - 1, b = j - 1;
        int d0 = (a / 14 - b / 14) + 13;
        int d1 = (a % 14 - b % 14) + 13;
        idx = d0 * 27 + d1;
    }
    g_rpb[tid] = rel_table[idx * Hh + h];
}

// ---------------------------------------------------------------------------
// Kernels 2 & 4: fp16 GEMM  C = A @ W^T (+bias)
// CTA tile 128x64, warp tile 32x32 (8 warps, 4m x 2n), KC=64, 2-stage cp.async.
// 3 CTA/SM (smem 55296 B, ~80 regs) -> 24 warps/SM for latency hiding.
// EPI==0: scatter q/k/v (q pre-scaled).  EPI==1: out = A@W^T + proj_b (fp32)
// ---------------------------------------------------------------------------
template <int EPI>
__global__ __launch_bounds__(256, 3) void gemm_f16(
    const __half* __restrict__ A, const __half* __restrict__ W,
    const float* __restrict__ b0v, const float* __restrict__ b1v,
    const float* __restrict__ b2v, float* __restrict__ out)
{
    constexpr int K = 768, KC = 64, NCHUNK = K / KC;   // 12
    constexpr int TSTR = 36;                           // u32 per row (32 data + 4)
    constexpr int ASTG = 128 * TSTR;                   // u32 per A stage
    constexpr int BSTG = 64 * TSTR;                    // u32 per B stage
    extern __shared__ unsigned gsm[];
    const unsigned as_base = (unsigned)__cvta_generic_to_shared(gsm);
    const unsigned bs_base = as_base + 2 * ASTG * 4;

    const int tid  = threadIdx.x;
    const int bm   = blockIdx.y * 128;
    const int bn   = blockIdx.x * 64;
    const int w    = tid >> 5, lane = tid & 31;
    const int wm   = w >> 1, wn = w & 1;
    const int m0w  = wm * 32, n0w = wn * 32;
    const int r    = lane >> 2, cg = lane & 3;

    const int a_row = (lane & 7) | (lane & 8);
    const int a_c4  = (lane & 16) >> 2;
    const int b_row = (lane & 7) | ((lane & 16) >> 1);
    const int b_c4  = (lane & 8) >> 1;

    // staging per chunk: A 128x8 chunks (4/thread), B 64x8 (2/thread)
    auto issue = [&](int chunk) {
        const int kc0 = chunk * KC;
        const unsigned ab = as_base + (chunk & 1) * ASTG * 4;
        const unsigned bb = bs_base + (chunk & 1) * BSTG * 4;
#pragma unroll
        for (int i = 0; i < 4; i++) {
            int s = tid + i * 256;
            int row = s >> 3, c4 = s & 7;
            int gm = bm + row;
            cp16p(ab + (row * TSTR + c4 * 4) * 4,
                  A + (size_t)gm * K + kc0 + c4 * 8,
                  (gm < M_TOT) ? 16u : 0u);
        }
#pragma unroll
        for (int i = 0; i < 2; i++) {
            int s = tid + i * 256;
            int row = s >> 3, c4 = s & 7;
            cp16(bb + (row * TSTR + c4 * 4) * 4,
                 W + (size_t)(bn + row) * K + kc0 + c4 * 8);
        }
        cp_commit();
    };

    float acc[2][4][4];
#pragma unroll
    for (int i = 0; i < 2; i++)
#pragma unroll
        for (int j = 0; j < 4; j++)
#pragma unroll
            for (int t = 0; t < 4; t++) acc[i][j][t] = 0.f;

    issue(0);

    for (int c = 0; c < NCHUNK; c++) {
        if (c + 1 < NCHUNK) { issue(c + 1); cp_wait<1>(); }
        else                { cp_wait<0>(); }
        __syncthreads();   // stage c ready for all

        const unsigned abuf = as_base + (c & 1) * ASTG * 4;
        const unsigned bbuf = bs_base + (c & 1) * BSTG * 4;
#pragma unroll
        for (int ks = 0; ks < 4; ks++) {               // 4 x k16 per chunk
            const int kb = ks * 8;
            unsigned af[2][4], bf[4][2];
#pragma unroll
            for (int mt = 0; mt < 2; mt++) {
                unsigned aaddr = abuf +
                    ((m0w + mt * 16 + a_row) * TSTR + kb + a_c4) * 4;
                ldsm_x4(af[mt][0], af[mt][1], af[mt][2], af[mt][3], aaddr);
            }
#pragma unroll
            for (int j = 0; j < 4; j += 2) {
                unsigned baddr = bbuf +
                    ((n0w + j * 8 + b_row) * TSTR + kb + b_c4) * 4;
                ldsm_x4(bf[j][0], bf[j][1], bf[j + 1][0], bf[j + 1][1], baddr);
            }
#pragma unroll
            for (int mt = 0; mt < 2; mt++)
#pragma unroll
                for (int nt = 0; nt < 4; nt++)
                    mma_f16(acc[mt][nt][0], acc[mt][nt][1],
                            acc[mt][nt][2], acc[mt][nt][3],
                            af[mt][0], af[mt][1], af[mt][2], af[mt][3],
                            bf[nt][0], bf[nt][1]);
        }
        __syncthreads();   // compute(c) done everywhere before buf reuse
    }

    // Epilogue
#pragma unroll
    for (int mt = 0; mt < 2; mt++) {
        int mbase = bm + m0w + mt * 16;
#pragma unroll
        for (int nt = 0; nt < 4; nt++) {
            int nbase = bn + n0w + nt * 8 + 2 * cg;
#pragma unroll
            for (int half = 0; half < 2; half++) {
                int row = mbase + r + half * 8;
                if (row >= M_TOT) continue;
                float v0 = acc[mt][nt][half * 2 + 0];
                float v1 = acc[mt][nt][half * 2 + 1];
                if (EPI == 1) {
                    *(float2*)&out[(size_t)row * Cc + nbase] =
                        make_float2(v0 + b0v[nbase], v1 + b0v[nbase + 1]);
                } else {
                    int bI = row / Nn, n = row % Nn;
                    int which = nbase / Cc;      // uniform per CTA (64 | 768)
                    int cc = nbase % Cc;
                    int h = cc >> 6, d = cc & 63;
                    size_t off = (((size_t)bI * Hh + h) * Nn + n) * Dd + d;
                    if (which == 0)
                        *(unsigned*)&g_q[off] = pack2((v0 + b0v[cc]) * 0.125f,
                                                      (v1 + b0v[cc + 1]) * 0.125f);
                    else if (which == 1)
                        *(unsigned*)&g_k[off] = pack2(v0 + b1v[cc], v1 + b1v[cc + 1]);
                    else
                        *(unsigned*)&g_v[off] = pack2(v0 + b2v[cc], v1 + b2v[cc + 1]);
                }
            }
        }
    }
}

// ---------------------------------------------------------------------------
// Kernel 3: fused attention v3 (unchanged from R12 — proven)
// ---------------------------------------------------------------------------
__global__ __launch_bounds__(256, 2) void attn_fused() {
    extern __shared__ unsigned smemu[];
    unsigned* Qs = smemu;                       // [64][36]
    unsigned* Ks = smemu + 64 * 36;             // [256][36]; V overlays after scores
    float*    Ss = (float*)(smemu + 64 * 36 + 256 * 36);  // [64][212]

    const unsigned qs_base = (unsigned)__cvta_generic_to_shared(Qs);
    const unsigned ks_base = (unsigned)__cvta_generic_to_shared(Ks);
    const unsigned ss_base = (unsigned)__cvta_generic_to_shared(Ss);

    const int bh = blockIdx.y, h = bh % Hh, bI = bh / Hh;
    const int m0 = blockIdx.x * 64;
    const int tid = threadIdx.x, lane = tid & 31, w = tid >> 5;
    const int wm = w >> 2;
    const int wn = w & 3;
    const int r = lane >> 2, cg = lane & 3;
    const __half* qb = g_q + (size_t)bh * Nn * Dd;
    const __half* kb = g_k + (size_t)bh * Nn * Dd;
    const __half* vb = g_v + (size_t)bh * Nn * Dd;

    const int a_row = (lane & 7) | (lane & 8);
    const int a_c4  = (lane & 16) >> 2;
    const int b_row = (lane & 7) | ((lane & 16) >> 1);
    const int b_c4  = (lane & 8) >> 1;

    for (int s = tid; s < 64 * 8; s += 256) {
        int row = s >> 3, c4 = s & 7;
        if (m0 + row < Nn)
            cp16(qs_base + (row * 36 + c4 * 4) * 4,
                 qb + (size_t)(m0 + row) * Dd + c4 * 8);
    }
    for (int s = tid; s < 197 * 8; s += 256) {
        int row = s >> 3, c4 = s & 7;
        cp16(ks_base + (row * 36 + c4 * 4) * 4,
             kb + (size_t)row * Dd + c4 * 8);
    }
    cp_commit();
    cp_wait<0>();
    __syncthreads();

    // ---- scores: k-outer, 4 n-tile accumulators live ----
    {
        float acc[4][2][2][4];
#pragma unroll
        for (int a = 0; a < 4; a++)
#pragma unroll
            for (int i = 0; i < 2; i++)
#pragma unroll
                for (int j = 0; j < 2; j++)
#pragma unroll
                    for (int t = 0; t < 4; t++) acc[a][i][j][t] = 0.f;

#pragma unroll
        for (int ks = 0; ks < 4; ks++) {
            const int kbu = ks * 8;
            unsigned af[2][4];
#pragma unroll
            for (int mt = 0; mt < 2; mt++) {
                unsigned aaddr = qs_base +
                    ((wm * 32 + mt * 16 + a_row) * 36 + kbu + a_c4) * 4;
                ldsm_x4(af[mt][0], af[mt][1], af[mt][2], af[mt][3], aaddr);
            }
#pragma unroll
            for (int nt0 = 0; nt0 < 4; nt0++) {
                unsigned bf[2][2];
                unsigned baddr = ks_base +
                    ((nt0 * 64 + wn * 16 + b_row) * 36 + kbu + b_c4) * 4;
                ldsm_x4(bf[0][0], bf[0][1], bf[1][0], bf[1][1], baddr);
#pragma unroll
                for (int mt = 0; mt < 2; mt++)
#pragma unroll
                    for (int nt = 0; nt < 2; nt++)
                        mma_f16(acc[nt0][mt][nt][0], acc[nt0][mt][nt][1],
                                acc[nt0][mt][nt][2], acc[nt0][mt][nt][3],
                                af[mt][0], af[mt][1], af[mt][2], af[mt][3],
                                bf[nt][0], bf[nt][1]);
            }
        }

#pragma unroll
        for (int nt0 = 0; nt0 < 4; nt0++) {
            const int n0 = nt0 * 64;
#pragma unroll
            for (int mt = 0; mt < 2; mt++) {
                int mlb = wm * 32 + mt * 16;
#pragma unroll
                for (int nt = 0; nt < 2; nt++) {
                    int nl = wn * 16 + nt * 8 + 2 * cg;
                    if (n0 + nl >= 208) continue;
#pragma unroll
                    for (int half = 0; half < 2; half++) {
                        int ml = mlb + r + half * 8;
                        int mg = m0 + ml;
                        float v0 = 0.f, v1 = 0.f;
                        if (mg < Nn) {
                            int ng0 = n0 + nl, ng1 = ng0 + 1;
                            const float* rp = g_rpb + ((size_t)h * Nn + mg) * Nn;
                            if (ng0 < Nn) v0 = acc[nt0][mt][nt][half * 2 + 0] + rp[ng0];
                            if (ng1 < Nn) v1 = acc[nt0][mt][nt][half * 2 + 1] + rp[ng1];
                        }
                        *(float2*)&Ss[ml * SLD + n0 + nl] = make_float2(v0, v1);
                    }
                }
            }
        }
    }
    __syncthreads();

    // ---- stage V (rows >= 197 zeroed — required for PV k-coverage 0..207) ----
    for (int s = tid; s < 208 * 8; s += 256) {
        int row = s >> 3, c4 = s & 7;
        if (row < Nn)
            cp16(ks_base + (row * 36 + c4 * 4) * 4,
                 vb + (size_t)row * Dd + c4 * 8);
        else
            *(uint4*)&Ks[row * 36 + c4 * 4] = make_uint4(0, 0, 0, 0);
    }
    cp_commit();

    // ---- softmax: vectorized float2, register-resident; pack to half2 ----
    for (int row = w; row < 64; row += 8) {
        float* sr = Ss + row * SLD;
        float2 v[4];
        float mx = -1e30f;
#pragma unroll
        for (int i = 0; i < 4; i++) {
            int j = lane + 32 * i;
            v[i] = (j < 104) ? *(float2*)&sr[2 * j] : make_float2(0.f, 0.f);
            if (2 * j < Nn)     mx = fmaxf(mx, v[i].x);
            if (2 * j + 1 < Nn) mx = fmaxf(mx, v[i].y);
        }
#pragma unroll
        for (int o = 16; o; o >>= 1) mx = fmaxf(mx, __shfl_xor_sync(0xffffffffu, mx, o));
        float s = 0.f;
#pragma unroll
        for (int i = 0; i < 4; i++) {
            int j = lane + 32 * i;
            float e0 = (2 * j < Nn)     ? __expf(v[i].x - mx) : 0.f;
            float e1 = (2 * j + 1 < Nn) ? __expf(v[i].y - mx) : 0.f;
            v[i].x = e0; v[i].y = e1;
            s += e0 + e1;
        }
#pragma unroll
        for (int o = 16; o; o >>= 1) s += __shfl_xor_sync(0xffffffffu, s, o);
        float inv = 1.f / s;
        unsigned* pu = (unsigned*)sr;
#pragma unroll
        for (int i = 0; i < 4; i++) {
            int j = lane + 32 * i;
            if (j < 104) pu[j] = pack2(v[i].x * inv, v[i].y * inv);
        }
    }

    cp_wait<0>();
    __syncthreads();

    // ---- PV: 13 k16-steps; V consumed via ldsm.trans ----
    float accO[2][2][4];
#pragma unroll
    for (int i = 0; i < 2; i++)
#pragma unroll
        for (int j = 0; j < 2; j++)
#pragma unroll
            for (int t = 0; t < 4; t++) accO[i][j][t] = 0.f;

#pragma unroll
    for (int kst = 0; kst < 13; kst++) {
        const int kbu = kst * 8;
        unsigned af[2][4], bf[2][2];
#pragma unroll
        for (int mt = 0; mt < 2; mt++) {
            unsigned aaddr = ss_base +
                ((wm * 32 + mt * 16 + a_row) * SLD + kbu + a_c4) * 4;
            ldsm_x4(af[mt][0], af[mt][1], af[mt][2], af[mt][3], aaddr);
        }
        {
            unsigned vaddr = ks_base +
                (((kst * 16 + (lane & 15)) * 36) + wn * 8 + ((lane >> 4) * 4)) * 4;
            ldsm_x4_trans(bf[0][0], bf[0][1], bf[1][0], bf[1][1], vaddr);
        }
#pragma unroll
        for (int mt = 0; mt < 2; mt++)
#pragma unroll
            for (int nt = 0; nt < 2; nt++)
                mma_f16(accO[mt][nt][0], accO[mt][nt][1],
                        accO[mt][nt][2], accO[mt][nt][3],
                        af[mt][0], af[mt][1], af[mt][2], af[mt][3],
                        bf[nt][0], bf[nt][1]);
    }

#pragma unroll
    for (int mt = 0; mt < 2; mt++) {
        int mbase = m0 + wm * 32 + mt * 16;
#pragma unroll
        for (int nt = 0; nt < 2; nt++) {
            int nb = wn * 16 + nt * 8 + 2 * cg;
#pragma unroll
            for (int half = 0; half < 2; half++) {
                int m = mbase + r + half * 8;
                if (m >= Nn) continue;
                size_t o = ((size_t)bI * Nn + m) * Cc + h * Dd + nb;
                *(unsigned*)&g_o[o] = pack2(accO[mt][nt][half * 2 + 0],
                                            accO[mt][nt][half * 2 + 1]);
            }
        }
    }
}

// ---------------------------------------------------------------------------
extern "C" void kernel_launch(void* const* d_in, const int* in_sizes, int n_in,
                              void* d_out, int out_size)
{
    const float* x         = (const float*)d_in[0];
    const float* qkv_w     = (const float*)d_in[1];
    const float* q_bias    = (const float*)d_in[2];
    const float* k_bias    = (const float*)d_in[3];
    const float* v_bias    = (const float*)d_in[4];
    const float* rel_table = (const float*)d_in[5];
    const float* proj_w    = (const float*)d_in[6];
    const float* proj_b    = (const float*)d_in[7];
    float* out = (float*)d_out;

    constexpr int GEMM_SMEM = (2 * 128 * 36 + 2 * 64 * 36) * 4;      // 55296
    constexpr int ATTN_SMEM = (64 * 36 + 256 * 36 + 64 * SLD) * 4;   // 100352

    static bool attr_done = false;
    if (!attr_done) {
        cudaFuncSetAttribute(gemm_f16<0>, cudaFuncAttributeMaxDynamicSharedMemorySize, GEMM_SMEM);
        cudaFuncSetAttribute(gemm_f16<1>, cudaFuncAttributeMaxDynamicSharedMemorySize, GEMM_SMEM);
        cudaFuncSetAttribute(attn_fused,  cudaFuncAttributeMaxDynamicSharedMemorySize, ATTN_SMEM);
        attr_done = true;
    }

    // Resolve DEVICE addresses of __device__ symbols.
    __half *d_xh, *d_wh, *d_pwh, *d_o;
    cudaGetSymbolAddress((void**)&d_xh,  g_xh);
    cudaGetSymbolAddress((void**)&d_wh,  g_wh);
    cudaGetSymbolAddress((void**)&d_pwh, g_pwh);
    cudaGetSymbolAddress((void**)&d_o,   g_o);

    // 0. fp32 -> fp16 conversions
    {
        int n4x = M_TOT * Cc / 4;
        cvt_kernel<<<(n4x + 255) / 256, 256>>>(x, d_xh, n4x);
        int n4w = 3 * Cc * Cc / 4;
        cvt_kernel<<<(n4w + 255) / 256, 256>>>(qkv_w, d_wh, n4w);
        int n4p = Cc * Cc / 4;
        cvt_kernel<<<(n4p + 255) / 256, 256>>>(proj_w, d_pwh, n4p);
    }
    // 1. relative position bias gather
    {
        int total = Hh * Nn * Nn;
        rpb_kernel<<<(total + 255) / 256, 256>>>(rel_table);
    }
    // 2. QKV projection + scatter
    {
        dim3 grid(3 * Cc / 64, (M_TOT + 127) / 128);
        gemm_f16<0><<<grid, 256, GEMM_SMEM>>>(d_xh, d_wh, q_bias, k_bias, v_bias, nullptr);
    }
    // 3. fused attention
    {
        dim3 grid((Nn + 63) / 64, Bb * Hh);
        attn_fused<<<grid, 256, ATTN_SMEM>>>();
    }
    // 4. output projection
    {
        dim3 grid(Cc / 64, (M_TOT + 127) / 128);
        gemm_f16<1><<<grid, 256, GEMM_SMEM>>>(d_o, d_pwh, proj_b,
                                              nullptr, nullptr, out);
    }
}

// round 15
// speedup vs baseline: 1.0214x; 1.0214x over previous
#include <cuda_runtime.h>
#include <cuda_fp16.h>
#include <cstddef>
#include <cstdint>

// Problem constants
constexpr int Bb  = 64;
constexpr int Nn  = 197;
constexpr int Cc  = 768;
constexpr int Hh  = 12;
constexpr int Dd  = 64;
constexpr int M_TOT = Bb * Nn;        // 12608
constexpr int SLD  = 212;             // S row stride (floats): 208 cols + 4 pad

// Scratch (device globals) — fp16
__device__ __half g_q[(size_t)Bb * Hh * Nn * Dd];
__device__ __half g_k[(size_t)Bb * Hh * Nn * Dd];
__device__ __half g_v[(size_t)Bb * Hh * Nn * Dd];
__device__ float  g_rpb[(size_t)Hh * Nn * Nn];
__device__ __half g_o[(size_t)Bb * Nn * Cc];
// pre-converted fp16 inputs
__device__ __half g_xh[(size_t)M_TOT * Cc];          // x
__device__ __half g_wh[(size_t)3 * Cc * Cc];         // qkv_w
__device__ __half g_pwh[(size_t)Cc * Cc];            // proj_w

// ---------------------------------------------------------------------------
// helpers
// ---------------------------------------------------------------------------
__device__ __forceinline__ unsigned pack2(float x, float y) {
    __half2 h = __float22half2_rn(make_float2(x, y));
    return *reinterpret_cast<unsigned*>(&h);
}

__device__ __forceinline__ void mma_f16(
    float& c0, float& c1, float& c2, float& c3,
    unsigned a0, unsigned a1, unsigned a2, unsigned a3,
    unsigned b0, unsigned b1)
{
    asm volatile(
        "mma.sync.aligned.m16n8k16.row.col.f32.f16.f16.f32 "
        "{%0,%1,%2,%3},{%4,%5,%6,%7},{%8,%9},{%0,%1,%2,%3};\n"
        : "+f"(c0), "+f"(c1), "+f"(c2), "+f"(c3)
        : "r"(a0), "r"(a1), "r"(a2), "r"(a3), "r"(b0), "r"(b1));
}

__device__ __forceinline__ void ldsm_x4(
    unsigned& r0, unsigned& r1, unsigned& r2, unsigned& r3, unsigned addr)
{
    asm volatile("ldmatrix.sync.aligned.m8n8.x4.shared.b16 {%0,%1,%2,%3}, [%4];"
                 : "=r"(r0), "=r"(r1), "=r"(r2), "=r"(r3) : "r"(addr));
}

__device__ __forceinline__ void ldsm_x4_trans(
    unsigned& r0, unsigned& r1, unsigned& r2, unsigned& r3, unsigned addr)
{
    asm volatile("ldmatrix.sync.aligned.m8n8.x4.trans.shared.b16 {%0,%1,%2,%3}, [%4];"
                 : "=r"(r0), "=r"(r1), "=r"(r2), "=r"(r3) : "r"(addr));
}

__device__ __forceinline__ void cp16(unsigned dst, const void* src) {
    asm volatile("cp.async.ca.shared.global [%0], [%1], 16;"
                 :: "r"(dst), "l"(src) : "memory");
}
// predicated: bytes==0 -> zero-fill destination
__device__ __forceinline__ void cp16p(unsigned dst, const void* src, unsigned bytes) {
    asm volatile("cp.async.ca.shared.global [%0], [%1], 16, %2;"
                 :: "r"(dst), "l"(src), "r"(bytes) : "memory");
}
__device__ __forceinline__ void cp_commit() {
    asm volatile("cp.async.commit_group;" ::: "memory");
}
template <int N>
__device__ __forceinline__ void cp_wait() {
    asm volatile("cp.async.wait_group %0;" :: "n"(N) : "memory");
}

// ---------------------------------------------------------------------------
// Kernel 0a: fp32 -> fp16 conversion of x AND qkv_w in ONE launch
// ---------------------------------------------------------------------------
__global__ void cvt_xw_kernel(const float* __restrict__ x,
                              const float* __restrict__ w,
                              __half* __restrict__ xh,
                              __half* __restrict__ wh,
                              int n4x, int n4tot) {
    int i = blockIdx.x * blockDim.x + threadIdx.x;
    if (i >= n4tot) return;
    if (i < n4x) {
        float4 f = ((const float4*)x)[i];
        ((uint2*)xh)[i] = make_uint2(pack2(f.x, f.y), pack2(f.z, f.w));
    } else {
        int j = i - n4x;
        float4 f = ((const float4*)w)[j];
        ((uint2*)wh)[j] = make_uint2(pack2(f.x, f.y), pack2(f.z, f.w));
    }
}

// Kernel 0b: proj_w conversion (needed only before gemm1; launched late)
__global__ void cvt_kernel(const float* __restrict__ src, __half* __restrict__ dst,
                           int n4) {
    int i = blockIdx.x * blockDim.x + threadIdx.x;
    if (i >= n4) return;
    float4 f = ((const float4*)src)[i];
    ((uint2*)dst)[i] = make_uint2(pack2(f.x, f.y), pack2(f.z, f.w));
}

// ---------------------------------------------------------------------------
// Kernel 1: relative position bias gather
// ---------------------------------------------------------------------------
__global__ void rpb_kernel(const float* __restrict__ rel_table) {
    int tid = blockIdx.x * blockDim.x + threadIdx.x;
    const int total = Hh * Nn * Nn;
    if (tid >= total) return;
    int h = tid / (Nn * Nn);
    int r = tid % (Nn * Nn);
    int i = r / Nn, j = r % Nn;
    int idx;
    if (i == 0 && j == 0)      idx = 731;
    else if (i == 0)           idx = 729;
    else if (j == 0)           idx = 730;
    else {
        int a = i - 1, b = j - 1;
        int d0 = (a / 14 - b / 14) + 13;
        int d1 = (a % 14 - b % 14) + 13;
        idx = d0 * 27 + d1;
    }
    g_rpb[tid] = rel_table[idx * Hh + h];
}

// ---------------------------------------------------------------------------
// Kernels 2 & 4: fp16 GEMM  C = A @ W^T (+bias)  — exact R12 configuration
// 3-stage cp.async pipeline, KC=32, BM=BN=128, 8 warps (4m x 2n), warp 32x64.
// smem: As[3][128][20] | Bs[3][128][20] u32 = 61440 B
// ---------------------------------------------------------------------------
template <int EPI>
__global__ __launch_bounds__(256, 2) void gemm_f16(
    const __half* __restrict__ A, const __half* __restrict__ W,
    const float* __restrict__ b0v, const float* __restrict__ b1v,
    const float* __restrict__ b2v, float* __restrict__ out)
{
    constexpr int K = 768, KC = 32, NCHUNK = K / KC;   // 24
    constexpr int TSTR = 20;                           // u32 per row
    constexpr int STG = 128 * TSTR;                    // 2560 u32 per matrix stage
    extern __shared__ unsigned gsm[];
    const unsigned as_base = (unsigned)__cvta_generic_to_shared(gsm);
    const unsigned bs_base = as_base + 3 * STG * 4;

    const int tid  = threadIdx.x;
    const int bm   = blockIdx.y * 128;
    const int bn   = blockIdx.x * 128;
    const int w    = tid >> 5, lane = tid & 31;
    const int wm   = w >> 1, wn = w & 1;
    const int m0w  = wm * 32, n0w = wn * 64;
    const int r    = lane >> 2, cg = lane & 3;

    const int a_row = (lane & 7) | (lane & 8);
    const int a_c4  = (lane & 16) >> 2;
    const int b_row = (lane & 7) | ((lane & 16) >> 1);
    const int b_c4  = (lane & 8) >> 1;

    // staging: 512 16B-chunks per matrix per stage, 2 per thread
    const int srow0 = tid >> 2;
    const int sch   = tid & 3;

    auto issue = [&](int chunk) {
        const int kc0 = chunk * KC;
        const unsigned ab = as_base + (chunk % 3) * STG * 4;
        const unsigned bb = bs_base + (chunk % 3) * STG * 4;
#pragma unroll
        for (int i = 0; i < 2; i++) {
            int row = srow0 + i * 64;
            int gm = bm + row;
            cp16p(ab + (row * TSTR + sch * 4) * 4,
                  A + (size_t)gm * K + kc0 + sch * 8,
                  (gm < M_TOT) ? 16u : 0u);
            cp16(bb + (row * TSTR + sch * 4) * 4,
                 W + (size_t)(bn + row) * K + kc0 + sch * 8);
        }
        cp_commit();
    };

    float acc[2][8][4];
#pragma unroll
    for (int i = 0; i < 2; i++)
#pragma unroll
        for (int j = 0; j < 8; j++)
#pragma unroll
            for (int t = 0; t < 4; t++) acc[i][j][t] = 0.f;

    issue(0);
    issue(1);

    for (int c = 0; c < NCHUNK; c++) {
        if (c + 1 < NCHUNK) cp_wait<1>(); else cp_wait<0>();
        __syncthreads();
        if (c + 2 < NCHUNK) issue(c + 2);

        const unsigned abuf = as_base + (c % 3) * STG * 4;
        const unsigned bbuf = bs_base + (c % 3) * STG * 4;
#pragma unroll
        for (int ks = 0; ks < 2; ks++) {
            const int kb = ks * 8;
            unsigned af[2][4], bf[8][2];
#pragma unroll
            for (int mt = 0; mt < 2; mt++) {
                unsigned aaddr = abuf +
                    ((m0w + mt * 16 + a_row) * TSTR + kb + a_c4) * 4;
                ldsm_x4(af[mt][0], af[mt][1], af[mt][2], af[mt][3], aaddr);
            }
#pragma unroll
            for (int j = 0; j < 8; j += 2) {
                unsigned baddr = bbuf +
                    ((n0w + j * 8 + b_row) * TSTR + kb + b_c4) * 4;
                ldsm_x4(bf[j][0], bf[j][1], bf[j + 1][0], bf[j + 1][1], baddr);
            }
#pragma unroll
            for (int mt = 0; mt < 2; mt++)
#pragma unroll
                for (int nt = 0; nt < 8; nt++)
                    mma_f16(acc[mt][nt][0], acc[mt][nt][1],
                            acc[mt][nt][2], acc[mt][nt][3],
                            af[mt][0], af[mt][1], af[mt][2], af[mt][3],
                            bf[nt][0], bf[nt][1]);
        }
        __syncthreads();
    }

    // Epilogue
#pragma unroll
    for (int mt = 0; mt < 2; mt++) {
        int mbase = bm + m0w + mt * 16;
#pragma unroll
        for (int nt = 0; nt < 8; nt++) {
            int nbase = bn + n0w + nt * 8 + 2 * cg;
#pragma unroll
            for (int half = 0; half < 2; half++) {
                int row = mbase + r + half * 8;
                if (row >= M_TOT) continue;
                float v0 = acc[mt][nt][half * 2 + 0];
                float v1 = acc[mt][nt][half * 2 + 1];
                if (EPI == 1) {
                    *(float2*)&out[(size_t)row * Cc + nbase] =
                        make_float2(v0 + b0v[nbase], v1 + b0v[nbase + 1]);
                } else {
                    int bI = row / Nn, n = row % Nn;
                    int which = nbase / Cc;
                    int cc = nbase % Cc;
                    int h = cc >> 6, d = cc & 63;
                    size_t off = (((size_t)bI * Hh + h) * Nn + n) * Dd + d;
                    if (which == 0)
                        *(unsigned*)&g_q[off] = pack2((v0 + b0v[cc]) * 0.125f,
                                                      (v1 + b0v[cc + 1]) * 0.125f);
                    else if (which == 1)
                        *(unsigned*)&g_k[off] = pack2(v0 + b1v[cc], v1 + b1v[cc + 1]);
                    else
                        *(unsigned*)&g_v[off] = pack2(v0 + b2v[cc], v1 + b2v[cc + 1]);
                }
            }
        }
    }
}

// ---------------------------------------------------------------------------
// Kernel 3: fused attention v3 (unchanged from R12 — proven)
// ---------------------------------------------------------------------------
__global__ __launch_bounds__(256, 2) void attn_fused() {
    extern __shared__ unsigned smemu[];
    unsigned* Qs = smemu;                       // [64][36]
    unsigned* Ks = smemu + 64 * 36;             // [256][36]; V overlays after scores
    float*    Ss = (float*)(smemu + 64 * 36 + 256 * 36);  // [64][212]

    const unsigned qs_base = (unsigned)__cvta_generic_to_shared(Qs);
    const unsigned ks_base = (unsigned)__cvta_generic_to_shared(Ks);
    const unsigned ss_base = (unsigned)__cvta_generic_to_shared(Ss);

    const int bh = blockIdx.y, h = bh % Hh, bI = bh / Hh;
    const int m0 = blockIdx.x * 64;
    const int tid = threadIdx.x, lane = tid & 31, w = tid >> 5;
    const int wm = w >> 2;
    const int wn = w & 3;
    const int r = lane >> 2, cg = lane & 3;
    const __half* qb = g_q + (size_t)bh * Nn * Dd;
    const __half* kb = g_k + (size_t)bh * Nn * Dd;
    const __half* vb = g_v + (size_t)bh * Nn * Dd;

    const int a_row = (lane & 7) | (lane & 8);
    const int a_c4  = (lane & 16) >> 2;
    const int b_row = (lane & 7) | ((lane & 16) >> 1);
    const int b_c4  = (lane & 8) >> 1;

    for (int s = tid; s < 64 * 8; s += 256) {
        int row = s >> 3, c4 = s & 7;
        if (m0 + row < Nn)
            cp16(qs_base + (row * 36 + c4 * 4) * 4,
                 qb + (size_t)(m0 + row) * Dd + c4 * 8);
    }
    for (int s = tid; s < 197 * 8; s += 256) {
        int row = s >> 3, c4 = s & 7;
        cp16(ks_base + (row * 36 + c4 * 4) * 4,
             kb + (size_t)row * Dd + c4 * 8);
    }
    cp_commit();
    cp_wait<0>();
    __syncthreads();

    // ---- scores: k-outer, 4 n-tile accumulators live ----
    {
        float acc[4][2][2][4];
#pragma unroll
        for (int a = 0; a < 4; a++)
#pragma unroll
            for (int i = 0; i < 2; i++)
#pragma unroll
                for (int j = 0; j < 2; j++)
#pragma unroll
                    for (int t = 0; t < 4; t++) acc[a][i][j][t] = 0.f;

#pragma unroll
        for (int ks = 0; ks < 4; ks++) {
            const int kbu = ks * 8;
            unsigned af[2][4];
#pragma unroll
            for (int mt = 0; mt < 2; mt++) {
                unsigned aaddr = qs_base +
                    ((wm * 32 + mt * 16 + a_row) * 36 + kbu + a_c4) * 4;
                ldsm_x4(af[mt][0], af[mt][1], af[mt][2], af[mt][3], aaddr);
            }
#pragma unroll
            for (int nt0 = 0; nt0 < 4; nt0++) {
                unsigned bf[2][2];
                unsigned baddr = ks_base +
                    ((nt0 * 64 + wn * 16 + b_row) * 36 + kbu + b_c4) * 4;
                ldsm_x4(bf[0][0], bf[0][1], bf[1][0], bf[1][1], baddr);
#pragma unroll
                for (int mt = 0; mt < 2; mt++)
#pragma unroll
                    for (int nt = 0; nt < 2; nt++)
                        mma_f16(acc[nt0][mt][nt][0], acc[nt0][mt][nt][1],
                                acc[nt0][mt][nt][2], acc[nt0][mt][nt][3],
                                af[mt][0], af[mt][1], af[mt][2], af[mt][3],
                                bf[nt][0], bf[nt][1]);
            }
        }

#pragma unroll
        for (int nt0 = 0; nt0 < 4; nt0++) {
            const int n0 = nt0 * 64;
#pragma unroll
            for (int mt = 0; mt < 2; mt++) {
                int mlb = wm * 32 + mt * 16;
#pragma unroll
                for (int nt = 0; nt < 2; nt++) {
                    int nl = wn * 16 + nt * 8 + 2 * cg;
                    if (n0 + nl >= 208) continue;
#pragma unroll
                    for (int half = 0; half < 2; half++) {
                        int ml = mlb + r + half * 8;
                        int mg = m0 + ml;
                        float v0 = 0.f, v1 = 0.f;
                        if (mg < Nn) {
                            int ng0 = n0 + nl, ng1 = ng0 + 1;
                            const float* rp = g_rpb + ((size_t)h * Nn + mg) * Nn;
                            if (ng0 < Nn) v0 = acc[nt0][mt][nt][half * 2 + 0] + rp[ng0];
                            if (ng1 < Nn) v1 = acc[nt0][mt][nt][half * 2 + 1] + rp[ng1];
                        }
                        *(float2*)&Ss[ml * SLD + n0 + nl] = make_float2(v0, v1);
                    }
                }
            }
        }
    }
    __syncthreads();

    // ---- stage V (rows >= 197 zeroed — required for PV k-coverage 0..207) ----
    for (int s = tid; s < 208 * 8; s += 256) {
        int row = s >> 3, c4 = s & 7;
        if (row < Nn)
            cp16(ks_base + (row * 36 + c4 * 4) * 4,
                 vb + (size_t)row * Dd + c4 * 8);
        else
            *(uint4*)&Ks[row * 36 + c4 * 4] = make_uint4(0, 0, 0, 0);
    }
    cp_commit();

    // ---- softmax: vectorized float2, register-resident; pack to half2 ----
    for (int row = w; row < 64; row += 8) {
        float* sr = Ss + row * SLD;
        float2 v[4];
        float mx = -1e30f;
#pragma unroll
        for (int i = 0; i < 4; i++) {
            int j = lane + 32 * i;
            v[i] = (j < 104) ? *(float2*)&sr[2 * j] : make_float2(0.f, 0.f);
            if (2 * j < Nn)     mx = fmaxf(mx, v[i].x);
            if (2 * j + 1 < Nn) mx = fmaxf(mx, v[i].y);
        }
#pragma unroll
        for (int o = 16; o; o >>= 1) mx = fmaxf(mx, __shfl_xor_sync(0xffffffffu, mx, o));
        float s = 0.f;
#pragma unroll
        for (int i = 0; i < 4; i++) {
            int j = lane + 32 * i;
            float e0 = (2 * j < Nn)     ? __expf(v[i].x - mx) : 0.f;
            float e1 = (2 * j + 1 < Nn) ? __expf(v[i].y - mx) : 0.f;
            v[i].x = e0; v[i].y = e1;
            s += e0 + e1;
        }
#pragma unroll
        for (int o = 16; o; o >>= 1) s += __shfl_xor_sync(0xffffffffu, s, o);
        float inv = 1.f / s;
        unsigned* pu = (unsigned*)sr;
#pragma unroll
        for (int i = 0; i < 4; i++) {
            int j = lane + 32 * i;
            if (j < 104) pu[j] = pack2(v[i].x * inv, v[i].y * inv);
        }
    }

    cp_wait<0>();
    __syncthreads();

    // ---- PV: 13 k16-steps; V consumed via ldsm.trans ----
    float accO[2][2][4];
#pragma unroll
    for (int i = 0; i < 2; i++)
#pragma unroll
        for (int j = 0; j < 2; j++)
#pragma unroll
            for (int t = 0; t < 4; t++) accO[i][j][t] = 0.f;

#pragma unroll
    for (int kst = 0; kst < 13; kst++) {
        const int kbu = kst * 8;
        unsigned af[2][4], bf[2][2];
#pragma unroll
        for (int mt = 0; mt < 2; mt++) {
            unsigned aaddr = ss_base +
                ((wm * 32 + mt * 16 + a_row) * SLD + kbu + a_c4) * 4;
            ldsm_x4(af[mt][0], af[mt][1], af[mt][2], af[mt][3], aaddr);
        }
        {
            unsigned vaddr = ks_base +
                (((kst * 16 + (lane & 15)) * 36) + wn * 8 + ((lane >> 4) * 4)) * 4;
            ldsm_x4_trans(bf[0][0], bf[0][1], bf[1][0], bf[1][1], vaddr);
        }
#pragma unroll
        for (int mt = 0; mt < 2; mt++)
#pragma unroll
            for (int nt = 0; nt < 2; nt++)
                mma_f16(accO[mt][nt][0], accO[mt][nt][1],
                        accO[mt][nt][2], accO[mt][nt][3],
                        af[mt][0], af[mt][1], af[mt][2], af[mt][3],
                        bf[nt][0], bf[nt][1]);
    }

#pragma unroll
    for (int mt = 0; mt < 2; mt++) {
        int mbase = m0 + wm * 32 + mt * 16;
#pragma unroll
        for (int nt = 0; nt < 2; nt++) {
            int nb = wn * 16 + nt * 8 + 2 * cg;
#pragma unroll
            for (int half = 0; half < 2; half++) {
                int m = mbase + r + half * 8;
                if (m >= Nn) continue;
                size_t o = ((size_t)bI * Nn + m) * Cc + h * Dd + nb;
                *(unsigned*)&g_o[o] = pack2(accO[mt][nt][half * 2 + 0],
                                            accO[mt][nt][half * 2 + 1]);
            }
        }
    }
}

// ---------------------------------------------------------------------------
extern "C" void kernel_launch(void* const* d_in, const int* in_sizes, int n_in,
                              void* d_out, int out_size)
{
    const float* x         = (const float*)d_in[0];
    const float* qkv_w     = (const float*)d_in[1];
    const float* q_bias    = (const float*)d_in[2];
    const float* k_bias    = (const float*)d_in[3];
    const float* v_bias    = (const float*)d_in[4];
    const float* rel_table = (const float*)d_in[5];
    const float* proj_w    = (const float*)d_in[6];
    const float* proj_b    = (const float*)d_in[7];
    float* out = (float*)d_out;

    constexpr int GEMM_SMEM = 6 * 128 * 20 * 4;                       // 61440
    constexpr int ATTN_SMEM = (64 * 36 + 256 * 36 + 64 * SLD) * 4;    // 100352

    static bool attr_done = false;
    if (!attr_done) {
        cudaFuncSetAttribute(gemm_f16<0>, cudaFuncAttributeMaxDynamicSharedMemorySize, GEMM_SMEM);
        cudaFuncSetAttribute(gemm_f16<1>, cudaFuncAttributeMaxDynamicSharedMemorySize, GEMM_SMEM);
        cudaFuncSetAttribute(attn_fused,  cudaFuncAttributeMaxDynamicSharedMemorySize, ATTN_SMEM);
        attr_done = true;
    }

    // Resolve DEVICE addresses of __device__ symbols.
    __half *d_xh, *d_wh, *d_pwh, *d_o;
    cudaGetSymbolAddress((void**)&d_xh,  g_xh);
    cudaGetSymbolAddress((void**)&d_wh,  g_wh);
    cudaGetSymbolAddress((void**)&d_pwh, g_pwh);
    cudaGetSymbolAddress((void**)&d_o,   g_o);

    // Launch order chosen so the 4th launch (ncu's capture target) is gemm0.
    // 1. fused conversion of x + qkv_w
    {
        int n4x = M_TOT * Cc / 4;
        int n4w = 3 * Cc * Cc / 4;
        int n4tot = n4x + n4w;
        cvt_xw_kernel<<<(n4tot + 255) / 256, 256>>>(x, qkv_w, d_xh, d_wh, n4x, n4tot);
    }
    // 2. proj_w conversion (only needed by gemm1, but harmless here)
    {
        int n4p = Cc * Cc / 4;
        cvt_kernel<<<(n4p + 255) / 256, 256>>>(proj_w, d_pwh, n4p);
    }
    // 3. relative position bias gather
    {
        int total = Hh * Nn * Nn;
        rpb_kernel<<<(total + 255) / 256, 256>>>(rel_table);
    }
    // 4. QKV projection + scatter  (<-- profiled launch)
    {
        dim3 grid(3 * Cc / 128, (M_TOT + 127) / 128);
        gemm_f16<0><<<grid, 256, GEMM_SMEM>>>(d_xh, d_wh, q_bias, k_bias, v_bias, nullptr);
    }
    // 5. fused attention
    {
        dim3 grid((Nn + 63) / 64, Bb * Hh);
        attn_fused<<<grid, 256, ATTN_SMEM>>>();
    }
    // 6. output projection
    {
        dim3 grid(Cc / 128, (M_TOT + 127) / 128);
        gemm_f16<1><<<grid, 256, GEMM_SMEM>>>(d_o, d_pwh, proj_b,
                                              nullptr, nullptr, out);
    }
}

// round 16
// speedup vs baseline: 1.0384x; 1.0166x over previous
#include <cuda_runtime.h>
#include <cuda_fp16.h>
#include <cstddef>
#include <cstdint>

// Problem constants
constexpr int Bb  = 64;
constexpr int Nn  = 197;
constexpr int Cc  = 768;
constexpr int Hh  = 12;
constexpr int Dd  = 64;
constexpr int M_TOT = Bb * Nn;        // 12608
constexpr int SLD  = 212;             // S row stride (floats): 208 cols + 4 pad

// Scratch (device globals) — fp16
__device__ __half g_q[(size_t)Bb * Hh * Nn * Dd];
__device__ __half g_k[(size_t)Bb * Hh * Nn * Dd];
__device__ __half g_v[(size_t)Bb * Hh * Nn * Dd];
__device__ float  g_rpb[(size_t)Hh * Nn * Nn];
__device__ __half g_o[(size_t)Bb * Nn * Cc];
// pre-converted fp16 inputs
__device__ __half g_xh[(size_t)M_TOT * Cc];          // x
__device__ __half g_wh[(size_t)3 * Cc * Cc];         // qkv_w
__device__ __half g_pwh[(size_t)Cc * Cc];            // proj_w

// ---------------------------------------------------------------------------
// helpers
// ---------------------------------------------------------------------------
__device__ __forceinline__ unsigned pack2(float x, float y) {
    __half2 h = __float22half2_rn(make_float2(x, y));
    return *reinterpret_cast<unsigned*>(&h);
}

__device__ __forceinline__ void mma_f16(
    float& c0, float& c1, float& c2, float& c3,
    unsigned a0, unsigned a1, unsigned a2, unsigned a3,
    unsigned b0, unsigned b1)
{
    asm volatile(
        "mma.sync.aligned.m16n8k16.row.col.f32.f16.f16.f32 "
        "{%0,%1,%2,%3},{%4,%5,%6,%7},{%8,%9},{%0,%1,%2,%3};\n"
        : "+f"(c0), "+f"(c1), "+f"(c2), "+f"(c3)
        : "r"(a0), "r"(a1), "r"(a2), "r"(a3), "r"(b0), "r"(b1));
}

__device__ __forceinline__ void ldsm_x4(
    unsigned& r0, unsigned& r1, unsigned& r2, unsigned& r3, unsigned addr)
{
    asm volatile("ldmatrix.sync.aligned.m8n8.x4.shared.b16 {%0,%1,%2,%3}, [%4];"
                 : "=r"(r0), "=r"(r1), "=r"(r2), "=r"(r3) : "r"(addr));
}

__device__ __forceinline__ void ldsm_x4_trans(
    unsigned& r0, unsigned& r1, unsigned& r2, unsigned& r3, unsigned addr)
{
    asm volatile("ldmatrix.sync.aligned.m8n8.x4.trans.shared.b16 {%0,%1,%2,%3}, [%4];"
                 : "=r"(r0), "=r"(r1), "=r"(r2), "=r"(r3) : "r"(addr));
}

__device__ __forceinline__ void cp16(unsigned dst, const void* src) {
    asm volatile("cp.async.ca.shared.global [%0], [%1], 16;"
                 :: "r"(dst), "l"(src) : "memory");
}
// predicated: bytes==0 -> zero-fill destination
__device__ __forceinline__ void cp16p(unsigned dst, const void* src, unsigned bytes) {
    asm volatile("cp.async.ca.shared.global [%0], [%1], 16, %2;"
                 :: "r"(dst), "l"(src), "r"(bytes) : "memory");
}
__device__ __forceinline__ void cp_commit() {
    asm volatile("cp.async.commit_group;" ::: "memory");
}
template <int N>
__device__ __forceinline__ void cp_wait() {
    asm volatile("cp.async.wait_group %0;" :: "n"(N) : "memory");
}

// ---------------------------------------------------------------------------
// Kernel 0: fp32 -> fp16 conversion of x, qkv_w, proj_w in ONE launch
// ---------------------------------------------------------------------------
__global__ void cvt_all_kernel(const float* __restrict__ x,
                               const float* __restrict__ w,
                               const float* __restrict__ pw,
                               __half* __restrict__ xh,
                               __half* __restrict__ wh,
                               __half* __restrict__ pwh,
                               int n4x, int n4xw, int n4tot) {
    int i = blockIdx.x * blockDim.x + threadIdx.x;
    if (i >= n4tot) return;
    const float* s; __half* d; int j;
    if (i < n4x)       { s = x;  d = xh;  j = i; }
    else if (i < n4xw) { s = w;  d = wh;  j = i - n4x; }
    else               { s = pw; d = pwh; j = i - n4xw; }
    float4 f = ((const float4*)s)[j];
    ((uint2*)d)[j] = make_uint2(pack2(f.x, f.y), pack2(f.z, f.w));
}

// ---------------------------------------------------------------------------
// Kernel 1: relative position bias gather
// ---------------------------------------------------------------------------
__global__ void rpb_kernel(const float* __restrict__ rel_table) {
    int tid = blockIdx.x * blockDim.x + threadIdx.x;
    const int total = Hh * Nn * Nn;
    if (tid >= total) return;
    int h = tid / (Nn * Nn);
    int r = tid % (Nn * Nn);
    int i = r / Nn, j = r % Nn;
    int idx;
    if (i == 0 && j == 0)      idx = 731;
    else if (i == 0)           idx = 729;
    else if (j == 0)           idx = 730;
    else {
        int a = i - 1, b = j - 1;
        int d0 = (a / 14 - b / 14) + 13;
        int d1 = (a % 14 - b % 14) + 13;
        idx = d0 * 27 + d1;
    }
    g_rpb[tid] = rel_table[idx * Hh + h];
}

// ---------------------------------------------------------------------------
// Kernels 2 & 4: fp16 GEMM  C = A @ W^T (+bias)  — measured-best R12 config
// 3-stage cp.async pipeline, KC=32, BM=BN=128, 8 warps (4m x 2n), warp 32x64.
// ---------------------------------------------------------------------------
template <int EPI>
__global__ __launch_bounds__(256, 2) void gemm_f16(
    const __half* __restrict__ A, const __half* __restrict__ W,
    const float* __restrict__ b0v, const float* __restrict__ b1v,
    const float* __restrict__ b2v, float* __restrict__ out)
{
    constexpr int K = 768, KC = 32, NCHUNK = K / KC;   // 24
    constexpr int TSTR = 20;
    constexpr int STG = 128 * TSTR;
    extern __shared__ unsigned gsm[];
    const unsigned as_base = (unsigned)__cvta_generic_to_shared(gsm);
    const unsigned bs_base = as_base + 3 * STG * 4;

    const int tid  = threadIdx.x;
    const int bm   = blockIdx.y * 128;
    const int bn   = blockIdx.x * 128;
    const int w    = tid >> 5, lane = tid & 31;
    const int wm   = w >> 1, wn = w & 1;
    const int m0w  = wm * 32, n0w = wn * 64;
    const int r    = lane >> 2, cg = lane & 3;

    const int a_row = (lane & 7) | (lane & 8);
    const int a_c4  = (lane & 16) >> 2;
    const int b_row = (lane & 7) | ((lane & 16) >> 1);
    const int b_c4  = (lane & 8) >> 1;

    const int srow0 = tid >> 2;
    const int sch   = tid & 3;

    auto issue = [&](int chunk) {
        const int kc0 = chunk * KC;
        const unsigned ab = as_base + (chunk % 3) * STG * 4;
        const unsigned bb = bs_base + (chunk % 3) * STG * 4;
#pragma unroll
        for (int i = 0; i < 2; i++) {
            int row = srow0 + i * 64;
            int gm = bm + row;
            cp16p(ab + (row * TSTR + sch * 4) * 4,
                  A + (size_t)gm * K + kc0 + sch * 8,
                  (gm < M_TOT) ? 16u : 0u);
            cp16(bb + (row * TSTR + sch * 4) * 4,
                 W + (size_t)(bn + row) * K + kc0 + sch * 8);
        }
        cp_commit();
    };

    float acc[2][8][4];
#pragma unroll
    for (int i = 0; i < 2; i++)
#pragma unroll
        for (int j = 0; j < 8; j++)
#pragma unroll
            for (int t = 0; t < 4; t++) acc[i][j][t] = 0.f;

    issue(0);
    issue(1);

    for (int c = 0; c < NCHUNK; c++) {
        if (c + 1 < NCHUNK) cp_wait<1>(); else cp_wait<0>();
        __syncthreads();
        if (c + 2 < NCHUNK) issue(c + 2);

        const unsigned abuf = as_base + (c % 3) * STG * 4;
        const unsigned bbuf = bs_base + (c % 3) * STG * 4;
#pragma unroll
        for (int ks = 0; ks < 2; ks++) {
            const int kb = ks * 8;
            unsigned af[2][4], bf[8][2];
#pragma unroll
            for (int mt = 0; mt < 2; mt++) {
                unsigned aaddr = abuf +
                    ((m0w + mt * 16 + a_row) * TSTR + kb + a_c4) * 4;
                ldsm_x4(af[mt][0], af[mt][1], af[mt][2], af[mt][3], aaddr);
            }
#pragma unroll
            for (int j = 0; j < 8; j += 2) {
                unsigned baddr = bbuf +
                    ((n0w + j * 8 + b_row) * TSTR + kb + b_c4) * 4;
                ldsm_x4(bf[j][0], bf[j][1], bf[j + 1][0], bf[j + 1][1], baddr);
            }
#pragma unroll
            for (int mt = 0; mt < 2; mt++)
#pragma unroll
                for (int nt = 0; nt < 8; nt++)
                    mma_f16(acc[mt][nt][0], acc[mt][nt][1],
                            acc[mt][nt][2], acc[mt][nt][3],
                            af[mt][0], af[mt][1], af[mt][2], af[mt][3],
                            bf[nt][0], bf[nt][1]);
        }
        __syncthreads();
    }

    // Epilogue
#pragma unroll
    for (int mt = 0; mt < 2; mt++) {
        int mbase = bm + m0w + mt * 16;
#pragma unroll
        for (int nt = 0; nt < 8; nt++) {
            int nbase = bn + n0w + nt * 8 + 2 * cg;
#pragma unroll
            for (int half = 0; half < 2; half++) {
                int row = mbase + r + half * 8;
                if (row >= M_TOT) continue;
                float v0 = acc[mt][nt][half * 2 + 0];
                float v1 = acc[mt][nt][half * 2 + 1];
                if (EPI == 1) {
                    *(float2*)&out[(size_t)row * Cc + nbase] =
                        make_float2(v0 + b0v[nbase], v1 + b0v[nbase + 1]);
                } else {
                    int bI = row / Nn, n = row % Nn;
                    int which = nbase / Cc;
                    int cc = nbase % Cc;
                    int h = cc >> 6, d = cc & 63;
                    size_t off = (((size_t)bI * Hh + h) * Nn + n) * Dd + d;
                    if (which == 0)
                        *(unsigned*)&g_q[off] = pack2((v0 + b0v[cc]) * 0.125f,
                                                      (v1 + b0v[cc + 1]) * 0.125f);
                    else if (which == 1)
                        *(unsigned*)&g_k[off] = pack2(v0 + b1v[cc], v1 + b1v[cc + 1]);
                    else
                        *(unsigned*)&g_v[off] = pack2(v0 + b2v[cc], v1 + b2v[cc + 1]);
                }
            }
        }
    }
}

// ---------------------------------------------------------------------------
// Kernel 3: fused attention v4 — 512 threads, 16 warps (4m x 4n),
// warp tile 16(m) x 16(n). Same smem layout / sync structure as v3.
// smem (u32): Qs[64][36] | Ks[256][36] (V overlays) | Ss[64][212] f32
// ---------------------------------------------------------------------------
__global__ __launch_bounds__(512, 2) void attn_fused() {
    extern __shared__ unsigned smemu[];
    unsigned* Qs = smemu;                       // [64][36]
    unsigned* Ks = smemu + 64 * 36;             // [256][36]; V overlays after scores
    float*    Ss = (float*)(smemu + 64 * 36 + 256 * 36);  // [64][212]

    const unsigned qs_base = (unsigned)__cvta_generic_to_shared(Qs);
    const unsigned ks_base = (unsigned)__cvta_generic_to_shared(Ks);
    const unsigned ss_base = (unsigned)__cvta_generic_to_shared(Ss);

    const int bh = blockIdx.y, h = bh % Hh, bI = bh / Hh;
    const int m0 = blockIdx.x * 64;
    const int tid = threadIdx.x, lane = tid & 31, w = tid >> 5;
    const int wm = w >> 2;          // 0..3 : 16 m-rows each
    const int wn = w & 3;           // 0..3 : 16 n-cols each
    const int r = lane >> 2, cg = lane & 3;
    const __half* qb = g_q + (size_t)bh * Nn * Dd;
    const __half* kb = g_k + (size_t)bh * Nn * Dd;
    const __half* vb = g_v + (size_t)bh * Nn * Dd;

    const int a_row = (lane & 7) | (lane & 8);
    const int a_c4  = (lane & 16) >> 2;
    const int b_row = (lane & 7) | ((lane & 16) >> 1);
    const int b_c4  = (lane & 8) >> 1;

    // ---- stage Q (64 rows: 512 chunks, exactly 1/thread) + K (197 rows) ----
    {
        int row = tid >> 3, c4 = tid & 7;
        if (m0 + row < Nn)
            cp16(qs_base + (row * 36 + c4 * 4) * 4,
                 qb + (size_t)(m0 + row) * Dd + c4 * 8);
    }
    for (int s = tid; s < 197 * 8; s += 512) {
        int row = s >> 3, c4 = s & 7;
        cp16(ks_base + (row * 36 + c4 * 4) * 4,
             kb + (size_t)row * Dd + c4 * 8);
    }
    cp_commit();
    cp_wait<0>();
    __syncthreads();

    // ---- scores: k-outer, 4 n-tile accumulators live; warp = 16m x 16n ----
    {
        float acc[4][2][4];             // [score n-tile][8-col group][frag]
#pragma unroll
        for (int a = 0; a < 4; a++)
#pragma unroll
            for (int j = 0; j < 2; j++)
#pragma unroll
                for (int t = 0; t < 4; t++) acc[a][j][t] = 0.f;

#pragma unroll
        for (int ks = 0; ks < 4; ks++) {
            const int kbu = ks * 8;
            unsigned af[4];
            {
                unsigned aaddr = qs_base +
                    ((wm * 16 + a_row) * 36 + kbu + a_c4) * 4;
                ldsm_x4(af[0], af[1], af[2], af[3], aaddr);
            }
#pragma unroll
            for (int nt0 = 0; nt0 < 4; nt0++) {
                unsigned bf[2][2];
                unsigned baddr = ks_base +
                    ((nt0 * 64 + wn * 16 + b_row) * 36 + kbu + b_c4) * 4;
                ldsm_x4(bf[0][0], bf[0][1], bf[1][0], bf[1][1], baddr);
#pragma unroll
                for (int nt = 0; nt < 2; nt++)
                    mma_f16(acc[nt0][nt][0], acc[nt0][nt][1],
                            acc[nt0][nt][2], acc[nt0][nt][3],
                            af[0], af[1], af[2], af[3],
                            bf[nt][0], bf[nt][1]);
            }
        }

        // write S tiles (+rpb); cols >= 208 skipped; invalid cells -> 0
#pragma unroll
        for (int nt0 = 0; nt0 < 4; nt0++) {
            const int n0 = nt0 * 64;
#pragma unroll
            for (int nt = 0; nt < 2; nt++) {
                int nl = wn * 16 + nt * 8 + 2 * cg;
                if (n0 + nl >= 208) continue;
#pragma unroll
                for (int half = 0; half < 2; half++) {
                    int ml = wm * 16 + r + half * 8;
                    int mg = m0 + ml;
                    float v0 = 0.f, v1 = 0.f;
                    if (mg < Nn) {
                        int ng0 = n0 + nl, ng1 = ng0 + 1;
                        const float* rp = g_rpb + ((size_t)h * Nn + mg) * Nn;
                        if (ng0 < Nn) v0 = acc[nt0][nt][half * 2 + 0] + rp[ng0];
                        if (ng1 < Nn) v1 = acc[nt0][nt][half * 2 + 1] + rp[ng1];
                    }
                    *(float2*)&Ss[ml * SLD + n0 + nl] = make_float2(v0, v1);
                }
            }
        }
    }
    __syncthreads();

    // ---- stage V (rows >= 197 zeroed — required for PV k-coverage 0..207) ----
    for (int s = tid; s < 208 * 8; s += 512) {
        int row = s >> 3, c4 = s & 7;
        if (row < Nn)
            cp16(ks_base + (row * 36 + c4 * 4) * 4,
                 vb + (size_t)row * Dd + c4 * 8);
        else
            *(uint4*)&Ks[row * 36 + c4 * 4] = make_uint4(0, 0, 0, 0);
    }
    cp_commit();

    // ---- softmax: vectorized float2, 4 rows per warp; pack to half2 ----
    for (int row = w; row < 64; row += 16) {
        float* sr = Ss + row * SLD;
        float2 v[4];
        float mx = -1e30f;
#pragma unroll
        for (int i = 0; i < 4; i++) {
            int j = lane + 32 * i;
            v[i] = (j < 104) ? *(float2*)&sr[2 * j] : make_float2(0.f, 0.f);
            if (2 * j < Nn)     mx = fmaxf(mx, v[i].x);
            if (2 * j + 1 < Nn) mx = fmaxf(mx, v[i].y);
        }
#pragma unroll
        for (int o = 16; o; o >>= 1) mx = fmaxf(mx, __shfl_xor_sync(0xffffffffu, mx, o));
        float s = 0.f;
#pragma unroll
        for (int i = 0; i < 4; i++) {
            int j = lane + 32 * i;
            float e0 = (2 * j < Nn)     ? __expf(v[i].x - mx) : 0.f;
            float e1 = (2 * j + 1 < Nn) ? __expf(v[i].y - mx) : 0.f;
            v[i].x = e0; v[i].y = e1;
            s += e0 + e1;
        }
#pragma unroll
        for (int o = 16; o; o >>= 1) s += __shfl_xor_sync(0xffffffffu, s, o);
        float inv = 1.f / s;
        unsigned* pu = (unsigned*)sr;
#pragma unroll
        for (int i = 0; i < 4; i++) {
            int j = lane + 32 * i;
            if (j < 104) pu[j] = pack2(v[i].x * inv, v[i].y * inv);
        }
    }

    cp_wait<0>();
    __syncthreads();

    // ---- PV: 13 k16-steps; warp = 16m x 16n; V via ldsm.trans ----
    float accO[2][4];
#pragma unroll
    for (int j = 0; j < 2; j++)
#pragma unroll
        for (int t = 0; t < 4; t++) accO[j][t] = 0.f;

#pragma unroll
    for (int kst = 0; kst < 13; kst++) {
        const int kbu = kst * 8;
        unsigned af[4], bf[2][2];
        {
            unsigned aaddr = ss_base +
                ((wm * 16 + a_row) * SLD + kbu + a_c4) * 4;
            ldsm_x4(af[0], af[1], af[2], af[3], aaddr);
        }
        {
            unsigned vaddr = ks_base +
                (((kst * 16 + (lane & 15)) * 36) + wn * 8 + ((lane >> 4) * 4)) * 4;
            ldsm_x4_trans(bf[0][0], bf[0][1], bf[1][0], bf[1][1], vaddr);
        }
#pragma unroll
        for (int nt = 0; nt < 2; nt++)
            mma_f16(accO[nt][0], accO[nt][1], accO[nt][2], accO[nt][3],
                    af[0], af[1], af[2], af[3],
                    bf[nt][0], bf[nt][1]);
    }

    // ---- store O tile (fp16) ----
#pragma unroll
    for (int nt = 0; nt < 2; nt++) {
        int nb = wn * 16 + nt * 8 + 2 * cg;
#pragma unroll
        for (int half = 0; half < 2; half++) {
            int m = m0 + wm * 16 + r + half * 8;
            if (m >= Nn) continue;
            size_t o = ((size_t)bI * Nn + m) * Cc + h * Dd + nb;
            *(unsigned*)&g_o[o] = pack2(accO[nt][half * 2 + 0],
                                        accO[nt][half * 2 + 1]);
        }
    }
}

// ---------------------------------------------------------------------------
extern "C" void kernel_launch(void* const* d_in, const int* in_sizes, int n_in,
                              void* d_out, int out_size)
{
    const float* x         = (const float*)d_in[0];
    const float* qkv_w     = (const float*)d_in[1];
    const float* q_bias    = (const float*)d_in[2];
    const float* k_bias    = (const float*)d_in[3];
    const float* v_bias    = (const float*)d_in[4];
    const float* rel_table = (const float*)d_in[5];
    const float* proj_w    = (const float*)d_in[6];
    const float* proj_b    = (const float*)d_in[7];
    float* out = (float*)d_out;

    constexpr int GEMM_SMEM = 6 * 128 * 20 * 4;                       // 61440
    constexpr int ATTN_SMEM = (64 * 36 + 256 * 36 + 64 * SLD) * 4;    // 100352

    static bool attr_done = false;
    if (!attr_done) {
        cudaFuncSetAttribute(gemm_f16<0>, cudaFuncAttributeMaxDynamicSharedMemorySize, GEMM_SMEM);
        cudaFuncSetAttribute(gemm_f16<1>, cudaFuncAttributeMaxDynamicSharedMemorySize, GEMM_SMEM);
        cudaFuncSetAttribute(attn_fused,  cudaFuncAttributeMaxDynamicSharedMemorySize, ATTN_SMEM);
        attr_done = true;
    }

    // Resolve DEVICE addresses of __device__ symbols.
    __half *d_xh, *d_wh, *d_pwh, *d_o;
    cudaGetSymbolAddress((void**)&d_xh,  g_xh);
    cudaGetSymbolAddress((void**)&d_wh,  g_wh);
    cudaGetSymbolAddress((void**)&d_pwh, g_pwh);
    cudaGetSymbolAddress((void**)&d_o,   g_o);

    // 1. fused conversion of x + qkv_w + proj_w (single launch)
    {
        int n4x  = M_TOT * Cc / 4;
        int n4xw = n4x + 3 * Cc * Cc / 4;
        int n4tot = n4xw + Cc * Cc / 4;
        cvt_all_kernel<<<(n4tot + 255) / 256, 256>>>(x, qkv_w, proj_w,
                                                     d_xh, d_wh, d_pwh,
                                                     n4x, n4xw, n4tot);
    }
    // 2. relative position bias gather
    {
        int total = Hh * Nn * Nn;
        rpb_kernel<<<(total + 255) / 256, 256>>>(rel_table);
    }
    // 3. QKV projection + scatter
    {
        dim3 grid(3 * Cc / 128, (M_TOT + 127) / 128);
        gemm_f16<0><<<grid, 256, GEMM_SMEM>>>(d_xh, d_wh, q_bias, k_bias, v_bias, nullptr);
    }
    // 4. fused attention  (<-- ncu capture target next round)
    {
        dim3 grid((Nn + 63) / 64, Bb * Hh);
        attn_fused<<<grid, 512, ATTN_SMEM>>>();
    }
    // 5. output projection
    {
        dim3 grid(Cc / 128, (M_TOT + 127) / 128);
        gemm_f16<1><<<grid, 256, GEMM_SMEM>>>(d_o, d_pwh, proj_b,
                                              nullptr, nullptr, out);
    }
}

// round 17
// speedup vs baseline: 1.1249x; 1.0833x over previous
#include <cuda_runtime.h>
#include <cuda_fp16.h>
#include <cstddef>
#include <cstdint>

// Problem constants
constexpr int Bb  = 64;
constexpr int Nn  = 197;
constexpr int Cc  = 768;
constexpr int Hh  = 12;
constexpr int Dd  = 64;
constexpr int M_TOT = Bb * Nn;        // 12608
constexpr int PSTR = 108;             // packed-P row stride (u32): 104 data + 4 pad

// Scratch (device globals) — fp16
__device__ __half g_q[(size_t)Bb * Hh * Nn * Dd];
__device__ __half g_k[(size_t)Bb * Hh * Nn * Dd];
__device__ __half g_v[(size_t)Bb * Hh * Nn * Dd];
__device__ float  g_rpb[(size_t)Hh * Nn * Nn];
__device__ __half g_o[(size_t)Bb * Nn * Cc];
// pre-converted fp16 inputs
__device__ __half g_xh[(size_t)M_TOT * Cc];          // x
__device__ __half g_wh[(size_t)3 * Cc * Cc];         // qkv_w
__device__ __half g_pwh[(size_t)Cc * Cc];            // proj_w

// ---------------------------------------------------------------------------
// helpers
// ---------------------------------------------------------------------------
__device__ __forceinline__ unsigned pack2(float x, float y) {
    __half2 h = __float22half2_rn(make_float2(x, y));
    return *reinterpret_cast<unsigned*>(&h);
}

__device__ __forceinline__ void mma_f16(
    float& c0, float& c1, float& c2, float& c3,
    unsigned a0, unsigned a1, unsigned a2, unsigned a3,
    unsigned b0, unsigned b1)
{
    asm volatile(
        "mma.sync.aligned.m16n8k16.row.col.f32.f16.f16.f32 "
        "{%0,%1,%2,%3},{%4,%5,%6,%7},{%8,%9},{%0,%1,%2,%3};\n"
        : "+f"(c0), "+f"(c1), "+f"(c2), "+f"(c3)
        : "r"(a0), "r"(a1), "r"(a2), "r"(a3), "r"(b0), "r"(b1));
}

__device__ __forceinline__ void ldsm_x4(
    unsigned& r0, unsigned& r1, unsigned& r2, unsigned& r3, unsigned addr)
{
    asm volatile("ldmatrix.sync.aligned.m8n8.x4.shared.b16 {%0,%1,%2,%3}, [%4];"
                 : "=r"(r0), "=r"(r1), "=r"(r2), "=r"(r3) : "r"(addr));
}

__device__ __forceinline__ void ldsm_x4_trans(
    unsigned& r0, unsigned& r1, unsigned& r2, unsigned& r3, unsigned addr)
{
    asm volatile("ldmatrix.sync.aligned.m8n8.x4.trans.shared.b16 {%0,%1,%2,%3}, [%4];"
                 : "=r"(r0), "=r"(r1), "=r"(r2), "=r"(r3) : "r"(addr));
}

__device__ __forceinline__ void cp16(unsigned dst, const void* src) {
    asm volatile("cp.async.ca.shared.global [%0], [%1], 16;"
                 :: "r"(dst), "l"(src) : "memory");
}
__device__ __forceinline__ void cp16p(unsigned dst, const void* src, unsigned bytes) {
    asm volatile("cp.async.ca.shared.global [%0], [%1], 16, %2;"
                 :: "r"(dst), "l"(src), "r"(bytes) : "memory");
}
__device__ __forceinline__ void cp_commit() {
    asm volatile("cp.async.commit_group;" ::: "memory");
}
template <int N>
__device__ __forceinline__ void cp_wait() {
    asm volatile("cp.async.wait_group %0;" :: "n"(N) : "memory");
}
__device__ __forceinline__ void bar_sync(int id, int cnt) {
    asm volatile("bar.sync %0, %1;" :: "r"(id), "r"(cnt) : "memory");
}

// ---------------------------------------------------------------------------
// Kernel 0: fp32 -> fp16 conversion of x, qkv_w, proj_w in ONE launch
// ---------------------------------------------------------------------------
__global__ void cvt_all_kernel(const float* __restrict__ x,
                               const float* __restrict__ w,
                               const float* __restrict__ pw,
                               __half* __restrict__ xh,
                               __half* __restrict__ wh,
                               __half* __restrict__ pwh,
                               int n4x, int n4xw, int n4tot) {
    int i = blockIdx.x * blockDim.x + threadIdx.x;
    if (i >= n4tot) return;
    const float* s; __half* d; int j;
    if (i < n4x)       { s = x;  d = xh;  j = i; }
    else if (i < n4xw) { s = w;  d = wh;  j = i - n4x; }
    else               { s = pw; d = pwh; j = i - n4xw; }
    float4 f = ((const float4*)s)[j];
    ((uint2*)d)[j] = make_uint2(pack2(f.x, f.y), pack2(f.z, f.w));
}

// ---------------------------------------------------------------------------
// Kernel 1: relative position bias gather
// ---------------------------------------------------------------------------
__global__ void rpb_kernel(const float* __restrict__ rel_table) {
    int tid = blockIdx.x * blockDim.x + threadIdx.x;
    const int total = Hh * Nn * Nn;
    if (tid >= total) return;
    int h = tid / (Nn * Nn);
    int r = tid % (Nn * Nn);
    int i = r / Nn, j = r % Nn;
    int idx;
    if (i == 0 && j == 0)      idx = 731;
    else if (i == 0)           idx = 729;
    else if (j == 0)           idx = 730;
    else {
        int a = i - 1, b = j - 1;
        int d0 = (a / 14 - b / 14) + 13;
        int d1 = (a % 14 - b % 14) + 13;
        idx = d0 * 27 + d1;
    }
    g_rpb[tid] = rel_table[idx * Hh + h];
}

// ---------------------------------------------------------------------------
// Kernels 2 & 4: fp16 GEMM  C = A @ W^T (+bias)  — measured-best R12 config
// ---------------------------------------------------------------------------
template <int EPI>
__global__ __launch_bounds__(256, 2) void gemm_f16(
    const __half* __restrict__ A, const __half* __restrict__ W,
    const float* __restrict__ b0v, const float* __restrict__ b1v,
    const float* __restrict__ b2v, float* __restrict__ out)
{
    constexpr int K = 768, KC = 32, NCHUNK = K / KC;   // 24
    constexpr int TSTR = 20;
    constexpr int STG = 128 * TSTR;
    extern __shared__ unsigned gsm[];
    const unsigned as_base = (unsigned)__cvta_generic_to_shared(gsm);
    const unsigned bs_base = as_base + 3 * STG * 4;

    const int tid  = threadIdx.x;
    const int bm   = blockIdx.y * 128;
    const int bn   = blockIdx.x * 128;
    const int w    = tid >> 5, lane = tid & 31;
    const int wm   = w >> 1, wn = w & 1;
    const int m0w  = wm * 32, n0w = wn * 64;
    const int r    = lane >> 2, cg = lane & 3;

    const int a_row = (lane & 7) | (lane & 8);
    const int a_c4  = (lane & 16) >> 2;
    const int b_row = (lane & 7) | ((lane & 16) >> 1);
    const int b_c4  = (lane & 8) >> 1;

    const int srow0 = tid >> 2;
    const int sch   = tid & 3;

    auto issue = [&](int chunk) {
        const int kc0 = chunk * KC;
        const unsigned ab = as_base + (chunk % 3) * STG * 4;
        const unsigned bb = bs_base + (chunk % 3) * STG * 4;
#pragma unroll
        for (int i = 0; i < 2; i++) {
            int row = srow0 + i * 64;
            int gm = bm + row;
            cp16p(ab + (row * TSTR + sch * 4) * 4,
                  A + (size_t)gm * K + kc0 + sch * 8,
                  (gm < M_TOT) ? 16u : 0u);
            cp16(bb + (row * TSTR + sch * 4) * 4,
                 W + (size_t)(bn + row) * K + kc0 + sch * 8);
        }
        cp_commit();
    };

    float acc[2][8][4];
#pragma unroll
    for (int i = 0; i < 2; i++)
#pragma unroll
        for (int j = 0; j < 8; j++)
#pragma unroll
            for (int t = 0; t < 4; t++) acc[i][j][t] = 0.f;

    issue(0);
    issue(1);

    for (int c = 0; c < NCHUNK; c++) {
        if (c + 1 < NCHUNK) cp_wait<1>(); else cp_wait<0>();
        __syncthreads();
        if (c + 2 < NCHUNK) issue(c + 2);

        const unsigned abuf = as_base + (c % 3) * STG * 4;
        const unsigned bbuf = bs_base + (c % 3) * STG * 4;
#pragma unroll
        for (int ks = 0; ks < 2; ks++) {
            const int kb = ks * 8;
            unsigned af[2][4], bf[8][2];
#pragma unroll
            for (int mt = 0; mt < 2; mt++) {
                unsigned aaddr = abuf +
                    ((m0w + mt * 16 + a_row) * TSTR + kb + a_c4) * 4;
                ldsm_x4(af[mt][0], af[mt][1], af[mt][2], af[mt][3], aaddr);
            }
#pragma unroll
            for (int j = 0; j < 8; j += 2) {
                unsigned baddr = bbuf +
                    ((n0w + j * 8 + b_row) * TSTR + kb + b_c4) * 4;
                ldsm_x4(bf[j][0], bf[j][1], bf[j + 1][0], bf[j + 1][1], baddr);
            }
#pragma unroll
            for (int mt = 0; mt < 2; mt++)
#pragma unroll
                for (int nt = 0; nt < 8; nt++)
                    mma_f16(acc[mt][nt][0], acc[mt][nt][1],
                            acc[mt][nt][2], acc[mt][nt][3],
                            af[mt][0], af[mt][1], af[mt][2], af[mt][3],
                            bf[nt][0], bf[nt][1]);
        }
        __syncthreads();
    }

    // Epilogue
#pragma unroll
    for (int mt = 0; mt < 2; mt++) {
        int mbase = bm + m0w + mt * 16;
#pragma unroll
        for (int nt = 0; nt < 8; nt++) {
            int nbase = bn + n0w + nt * 8 + 2 * cg;
#pragma unroll
            for (int half = 0; half < 2; half++) {
                int row = mbase + r + half * 8;
                if (row >= M_TOT) continue;
                float v0 = acc[mt][nt][half * 2 + 0];
                float v1 = acc[mt][nt][half * 2 + 1];
                if (EPI == 1) {
                    *(float2*)&out[(size_t)row * Cc + nbase] =
                        make_float2(v0 + b0v[nbase], v1 + b0v[nbase + 1]);
                } else {
                    int bI = row / Nn, n = row % Nn;
                    int which = nbase / Cc;
                    int cc = nbase % Cc;
                    int h = cc >> 6, d = cc & 63;
                    size_t off = (((size_t)bI * Hh + h) * Nn + n) * Dd + d;
                    if (which == 0)
                        *(unsigned*)&g_q[off] = pack2((v0 + b0v[cc]) * 0.125f,
                                                      (v1 + b0v[cc + 1]) * 0.125f);
                    else if (which == 1)
                        *(unsigned*)&g_k[off] = pack2(v0 + b1v[cc], v1 + b1v[cc + 1]);
                    else
                        *(unsigned*)&g_v[off] = pack2(v0 + b2v[cc], v1 + b2v[cc + 1]);
                }
            }
        }
    }
}

// ---------------------------------------------------------------------------
// Kernel 3: fused attention v5 — register-resident softmax (no fp32 S buffer).
// 512 threads, 16 warps (4m x 4n), warp tile 16(m) x 16(n of scores).
// smem (u32): Qs[64][36] | Ks[256][36] (V overlays) | Ps[64][108] | red[512]
// total 75776 B
// ---------------------------------------------------------------------------
__global__ __launch_bounds__(512, 2) void attn_fused() {
    extern __shared__ unsigned smemu[];
    unsigned* Qs = smemu;                          // [64][36]
    unsigned* Ks = smemu + 64 * 36;                // [256][36]; V overlays
    unsigned* Ps = smemu + 64 * 36 + 256 * 36;     // [64][108] packed half2 P
    float*  redM = (float*)(Ps + 64 * PSTR);       // [64][4]
    float*  redS = redM + 256;                     // [64][4]

    const unsigned qs_base = (unsigned)__cvta_generic_to_shared(Qs);
    const unsigned ks_base = (unsigned)__cvta_generic_to_shared(Ks);
    const unsigned ps_base = (unsigned)__cvta_generic_to_shared(Ps);

    const int bh = blockIdx.y, h = bh % Hh, bI = bh / Hh;
    const int m0 = blockIdx.x * 64;
    const int tid = threadIdx.x, lane = tid & 31, w = tid >> 5;
    const int wm = w >> 2;          // 0..3 : 16 m-rows
    const int wn = w & 3;           // 0..3 : 16 n-cols (score tokens)
    const int r = lane >> 2, cg = lane & 3;
    const __half* qb = g_q + (size_t)bh * Nn * Dd;
    const __half* kb = g_k + (size_t)bh * Nn * Dd;
    const __half* vb = g_v + (size_t)bh * Nn * Dd;

    const int a_row = (lane & 7) | (lane & 8);
    const int a_c4  = (lane & 16) >> 2;
    const int b_row = (lane & 7) | ((lane & 16) >> 1);
    const int b_c4  = (lane & 8) >> 1;

    // ---- stage Q (64 rows) + K (197 rows) via cp.async ----
    {
        int row = tid >> 3, c4 = tid & 7;
        if (m0 + row < Nn)
            cp16(qs_base + (row * 36 + c4 * 4) * 4,
                 qb + (size_t)(m0 + row) * Dd + c4 * 8);
    }
    for (int s = tid; s < 197 * 8; s += 512) {
        int row = s >> 3, c4 = s & 7;
        cp16(ks_base + (row * 36 + c4 * 4) * 4,
             kb + (size_t)row * Dd + c4 * 8);
    }
    cp_commit();
    cp_wait<0>();
    __syncthreads();

    // ---- scores: k-outer, 4 n-tile accumulators live ----
    float acc[4][2][4];
#pragma unroll
    for (int a = 0; a < 4; a++)
#pragma unroll
        for (int j = 0; j < 2; j++)
#pragma unroll
            for (int t = 0; t < 4; t++) acc[a][j][t] = 0.f;

#pragma unroll
    for (int ks = 0; ks < 4; ks++) {
        const int kbu = ks * 8;
        unsigned af[4];
        {
            unsigned aaddr = qs_base + ((wm * 16 + a_row) * 36 + kbu + a_c4) * 4;
            ldsm_x4(af[0], af[1], af[2], af[3], aaddr);
        }
#pragma unroll
        for (int nt0 = 0; nt0 < 4; nt0++) {
            unsigned bf[2][2];
            unsigned baddr = ks_base +
                ((nt0 * 64 + wn * 16 + b_row) * 36 + kbu + b_c4) * 4;
            ldsm_x4(bf[0][0], bf[0][1], bf[1][0], bf[1][1], baddr);
#pragma unroll
            for (int nt = 0; nt < 2; nt++)
                mma_f16(acc[nt0][nt][0], acc[nt0][nt][1],
                        acc[nt0][nt][2], acc[nt0][nt][3],
                        af[0], af[1], af[2], af[3],
                        bf[nt][0], bf[nt][1]);
        }
    }

    // ---- rpb add + column masking, in registers ----
    {
        const int mg0 = m0 + wm * 16 + r;
        const int mg1 = mg0 + 8;
        const float* rp0 = g_rpb + ((size_t)h * Nn + (mg0 < Nn ? mg0 : Nn - 1)) * Nn;
        const float* rp1 = g_rpb + ((size_t)h * Nn + (mg1 < Nn ? mg1 : Nn - 1)) * Nn;
#pragma unroll
        for (int nt0 = 0; nt0 < 4; nt0++)
#pragma unroll
            for (int nt = 0; nt < 2; nt++)
#pragma unroll
                for (int e = 0; e < 2; e++) {
                    int ng = nt0 * 64 + wn * 16 + nt * 8 + 2 * cg + e;
                    if (ng < Nn) {
                        acc[nt0][nt][e]     += rp0[ng];
                        acc[nt0][nt][2 + e] += rp1[ng];
                    } else {
                        acc[nt0][nt][e]     = -1e30f;
                        acc[nt0][nt][2 + e] = -1e30f;
                    }
                }
    }
    __syncthreads();   // all K reads done -> V may overlay Ks

    // ---- stage V (rows >= 197 zeroed; PV covers tokens 0..207) ----
    for (int s = tid; s < 208 * 8; s += 512) {
        int row = s >> 3, c4 = s & 7;
        if (row < Nn)
            cp16(ks_base + (row * 36 + c4 * 4) * 4,
                 vb + (size_t)row * Dd + c4 * 8);
        else
            *(uint4*)&Ks[row * 36 + c4 * 4] = make_uint4(0, 0, 0, 0);
    }
    cp_commit();

    // ---- register softmax: rows (wm*16+r) and (+8) ----
    float mx0 = -1e30f, mx1 = -1e30f;
#pragma unroll
    for (int nt0 = 0; nt0 < 4; nt0++)
#pragma unroll
        for (int nt = 0; nt < 2; nt++) {
            mx0 = fmaxf(mx0, fmaxf(acc[nt0][nt][0], acc[nt0][nt][1]));
            mx1 = fmaxf(mx1, fmaxf(acc[nt0][nt][2], acc[nt0][nt][3]));
        }
    mx0 = fmaxf(mx0, __shfl_xor_sync(0xffffffffu, mx0, 1));
    mx0 = fmaxf(mx0, __shfl_xor_sync(0xffffffffu, mx0, 2));
    mx1 = fmaxf(mx1, __shfl_xor_sync(0xffffffffu, mx1, 1));
    mx1 = fmaxf(mx1, __shfl_xor_sync(0xffffffffu, mx1, 2));
    if (cg == 0) {
        redM[(wm * 16 + r) * 4 + wn]     = mx0;
        redM[(wm * 16 + r + 8) * 4 + wn] = mx1;
    }
    bar_sync(1 + wm, 128);
    {
        float4 a = *(float4*)&redM[(wm * 16 + r) * 4];
        mx0 = fmaxf(fmaxf(a.x, a.y), fmaxf(a.z, a.w));
        float4 b = *(float4*)&redM[(wm * 16 + r + 8) * 4];
        mx1 = fmaxf(fmaxf(b.x, b.y), fmaxf(b.z, b.w));
    }
    float s0 = 0.f, s1 = 0.f;
#pragma unroll
    for (int nt0 = 0; nt0 < 4; nt0++)
#pragma unroll
        for (int nt = 0; nt < 2; nt++) {
            float e0 = __expf(acc[nt0][nt][0] - mx0);
            float e1 = __expf(acc[nt0][nt][1] - mx0);
            float e2 = __expf(acc[nt0][nt][2] - mx1);
            float e3 = __expf(acc[nt0][nt][3] - mx1);
            acc[nt0][nt][0] = e0; acc[nt0][nt][1] = e1;
            acc[nt0][nt][2] = e2; acc[nt0][nt][3] = e3;
            s0 += e0 + e1; s1 += e2 + e3;
        }
    s0 += __shfl_xor_sync(0xffffffffu, s0, 1);
    s0 += __shfl_xor_sync(0xffffffffu, s0, 2);
    s1 += __shfl_xor_sync(0xffffffffu, s1, 1);
    s1 += __shfl_xor_sync(0xffffffffu, s1, 2);
    if (cg == 0) {
        redS[(wm * 16 + r) * 4 + wn]     = s0;
        redS[(wm * 16 + r + 8) * 4 + wn] = s1;
    }
    bar_sync(1 + wm, 128);
    float inv0, inv1;
    {
        float4 a = *(float4*)&redS[(wm * 16 + r) * 4];
        inv0 = 1.f / (a.x + a.y + a.z + a.w);
        float4 b = *(float4*)&redS[(wm * 16 + r + 8) * 4];
        inv1 = 1.f / (b.x + b.y + b.z + b.w);
    }

    // ---- pack P (half2) into Ps ----
#pragma unroll
    for (int nt0 = 0; nt0 < 4; nt0++)
#pragma unroll
        for (int nt = 0; nt < 2; nt++) {
            int col = nt0 * 64 + wn * 16 + nt * 8 + 2 * cg;
            if (col < 208) {
                int cp = col >> 1;
                Ps[(wm * 16 + r) * PSTR + cp] =
                    pack2(acc[nt0][nt][0] * inv0, acc[nt0][nt][1] * inv0);
                Ps[(wm * 16 + r + 8) * PSTR + cp] =
                    pack2(acc[nt0][nt][2] * inv1, acc[nt0][nt][3] * inv1);
            }
        }

    cp_wait<0>();
    __syncthreads();   // V staged; Ps visible to all

    // ---- PV: 13 k16-steps; warp = 16m x 16d; V via ldsm.trans ----
    float accO[2][4];
#pragma unroll
    for (int j = 0; j < 2; j++)
#pragma unroll
        for (int t = 0; t < 4; t++) accO[j][t] = 0.f;

#pragma unroll
    for (int kst = 0; kst < 13; kst++) {
        const int kbu = kst * 8;
        unsigned af[4], bf[2][2];
        {
            unsigned aaddr = ps_base + ((wm * 16 + a_row) * PSTR + kbu + a_c4) * 4;
            ldsm_x4(af[0], af[1], af[2], af[3], aaddr);
        }
        {
            unsigned vaddr = ks_base +
                (((kst * 16 + (lane & 15)) * 36) + wn * 8 + ((lane >> 4) * 4)) * 4;
            ldsm_x4_trans(bf[0][0], bf[0][1], bf[1][0], bf[1][1], vaddr);
        }
#pragma unroll
        for (int nt = 0; nt < 2; nt++)
            mma_f16(accO[nt][0], accO[nt][1], accO[nt][2], accO[nt][3],
                    af[0], af[1], af[2], af[3],
                    bf[nt][0], bf[nt][1]);
    }

    // ---- store O tile (fp16) ----
#pragma unroll
    for (int nt = 0; nt < 2; nt++) {
        int nb = wn * 16 + nt * 8 + 2 * cg;
#pragma unroll
        for (int half = 0; half < 2; half++) {
            int m = m0 + wm * 16 + r + half * 8;
            if (m >= Nn) continue;
            size_t o = ((size_t)bI * Nn + m) * Cc + h * Dd + nb;
            *(unsigned*)&g_o[o] = pack2(accO[nt][half * 2 + 0],
                                        accO[nt][half * 2 + 1]);
        }
    }
}

// ---------------------------------------------------------------------------
extern "C" void kernel_launch(void* const* d_in, const int* in_sizes, int n_in,
                              void* d_out, int out_size)
{
    const float* x         = (const float*)d_in[0];
    const float* qkv_w     = (const float*)d_in[1];
    const float* q_bias    = (const float*)d_in[2];
    const float* k_bias    = (const float*)d_in[3];
    const float* v_bias    = (const float*)d_in[4];
    const float* rel_table = (const float*)d_in[5];
    const float* proj_w    = (const float*)d_in[6];
    const float* proj_b    = (const float*)d_in[7];
    float* out = (float*)d_out;

    constexpr int GEMM_SMEM = 6 * 128 * 20 * 4;                        // 61440
    constexpr int ATTN_SMEM = (64 * 36 + 256 * 36 + 64 * PSTR + 512) * 4; // 75776

    static bool attr_done = false;
    if (!attr_done) {
        cudaFuncSetAttribute(gemm_f16<0>, cudaFuncAttributeMaxDynamicSharedMemorySize, GEMM_SMEM);
        cudaFuncSetAttribute(gemm_f16<1>, cudaFuncAttributeMaxDynamicSharedMemorySize, GEMM_SMEM);
        cudaFuncSetAttribute(attn_fused,  cudaFuncAttributeMaxDynamicSharedMemorySize, ATTN_SMEM);
        attr_done = true;
    }

    // Resolve DEVICE addresses of __device__ symbols.
    __half *d_xh, *d_wh, *d_pwh, *d_o;
    cudaGetSymbolAddress((void**)&d_xh,  g_xh);
    cudaGetSymbolAddress((void**)&d_wh,  g_wh);
    cudaGetSymbolAddress((void**)&d_pwh, g_pwh);
    cudaGetSymbolAddress((void**)&d_o,   g_o);

    // 1. fused conversion of x + qkv_w + proj_w
    {
        int n4x  = M_TOT * Cc / 4;
        int n4xw = n4x + 3 * Cc * Cc / 4;
        int n4tot = n4xw + Cc * Cc / 4;
        cvt_all_kernel<<<(n4tot + 255) / 256, 256>>>(x, qkv_w, proj_w,
                                                     d_xh, d_wh, d_pwh,
                                                     n4x, n4xw, n4tot);
    }
    // 2. relative position bias gather
    {
        int total = Hh * Nn * Nn;
        rpb_kernel<<<(total + 255) / 256, 256>>>(rel_table);
    }
    // 3. QKV projection + scatter
    {
        dim3 grid(3 * Cc / 128, (M_TOT + 127) / 128);
        gemm_f16<0><<<grid, 256, GEMM_SMEM>>>(d_xh, d_wh, q_bias, k_bias, v_bias, nullptr);
    }
    // 4. fused attention  (<-- ncu capture target)
    {
        dim3 grid((Nn + 63) / 64, Bb * Hh);
        attn_fused<<<grid, 512, ATTN_SMEM>>>();
    }
    // 5. output projection
    {
        dim3 grid(Cc / 128, (M_TOT + 127) / 128);
        gemm_f16<1><<<grid, 256, GEMM_SMEM>>>(d_o, d_pwh, proj_b,
                                              nullptr, nullptr, out);
    }
}